// round 3
// baseline (speedup 1.0000x reference)
#include <cuda_runtime.h>
#include <cuda_bf16.h>
#include <mma.h>
#include <math.h>

using namespace nvcuda;

#define SEQ     2048
#define EMBD    1024
#define STATE   1024
#define QIN     2048
#define QUERY   256
#define NKB     10000
#define VALUE   512
#define LSTMIN  1536
#define DECIN   2560
#define NTOK    32000
#define NB      148
#define NT      512

// ---------------- device scratch (no allocations allowed) ----------------
__device__ __align__(16) float g_dec_in[SEQ * DECIN];   // [emb | kb_out | lstm_states] fp32
__device__ __align__(16) __nv_bfloat16 g_dec_bf[SEQ * DECIN];
__device__ __align__(16) float g_A1[SEQ * QIN];
__device__ __align__(16) float g_Gx[SEQ * 4 * STATE];
__device__ __align__(16) __nv_bfloat16 g_Wq1T_bf[QIN * STATE];   // [2048 out][1024 k]
__device__ __align__(16) __nv_bfloat16 g_Wq2T_bf[QUERY * QIN];   // [256 out][2048 k]
__device__ __align__(16) __nv_bfloat16 g_kbk_bf[NKB * QUERY];
__device__ __align__(16) __nv_bfloat16 g_kbv_bf[NKB * VALUE];
__device__ __align__(16) __nv_bfloat16 g_Wihv_bf[4 * STATE * VALUE]; // W_ih[:,1024:1536]
__device__ __align__(16) __nv_bfloat16 g_Whh_bf[4 * STATE * STATE];
__device__ __align__(16) __nv_bfloat16 g_Wdec_bf[NTOK * DECIN];
__device__ __align__(16) float g_qh[QIN];
__device__ __align__(16) float g_q[QUERY];
__device__ __align__(16) float g_pval[VALUE * 152];
__device__ __align__(16) float g_pz[NB];
__device__ __align__(16) float g_val[VALUE];
__device__ float g_invZ;
__device__ __align__(16) float g_hxA[STATE];
__device__ __align__(16) float g_hxB[STATE];
__device__ __align__(16) float g_cx[STATE];
__device__ volatile unsigned g_gen;
__device__ volatile unsigned g_arr[NB];

// ---------------- helpers ----------------
__device__ __forceinline__ float dot4(float4 a, float4 b) {
    return a.x * b.x + a.y * b.y + a.z * b.z + a.w * b.w;
}
// 8 bf16 (as uint4) dotted with 8 fp32 (two float4)
__device__ __forceinline__ float bdot(uint4 u, float4 a, float4 b) {
    float2 p; float s;
    p = __bfloat1622float2(*(const __nv_bfloat162*)&u.x); s  = p.x * a.x + p.y * a.y;
    p = __bfloat1622float2(*(const __nv_bfloat162*)&u.y); s += p.x * a.z + p.y * a.w;
    p = __bfloat1622float2(*(const __nv_bfloat162*)&u.z); s += p.x * b.x + p.y * b.y;
    p = __bfloat1622float2(*(const __nv_bfloat162*)&u.w); s += p.x * b.z + p.y * b.w;
    return s;
}
__device__ __forceinline__ float sigmoidf_(float x) { return 1.0f / (1.0f + expf(-x)); }
__device__ __forceinline__ float wred(float a) {
#pragma unroll
    for (int o = 16; o; o >>= 1) a += __shfl_xor_sync(0xffffffffu, a, o);
    return a;
}

// flag-array grid barrier: per-block arrival store, block-0 warp-0 polls, broadcast.
__device__ __forceinline__ void grid_sync(unsigned &tgt, int b) {
    __syncthreads();
    const int tid = threadIdx.x;
    if (tid == 0) { __threadfence(); g_arr[b] = tgt; }
    if (b == 0 && tid < 32) {
        bool done = false;
        while (!done) {
            bool mine = true;
            for (int i = tid; i < NB; i += 32)
                if (g_arr[i] != tgt) mine = false;
            done = __all_sync(0xffffffffu, mine);
        }
        if (tid == 0) { __threadfence(); g_gen = tgt; }
    }
    if (tid == 0) {
        while (g_gen != tgt) { }
        __threadfence();   // CCTL.IVALL: invalidate this SM's L1 so data reads see L2
    }
    __syncthreads();
    tgt++;
}

// ---------------- embedding gather + state init ----------------
__global__ void embed_init_kernel(const int* __restrict__ ids,
                                  const float* __restrict__ encW) {
    int t = blockIdx.x;
    int id = ids[t];
    for (int e = threadIdx.x; e < EMBD; e += blockDim.x)
        g_dec_in[(size_t)t * DECIN + e] = encW[(size_t)id * EMBD + e];
    if (blockIdx.x == 0) {
        for (int i = threadIdx.x; i < STATE; i += blockDim.x) {
            g_hxA[i] = 0.0f; g_hxB[i] = 0.0f; g_cx[i] = 0.0f;
        }
    }
}

// ---------------- transpose + convert: dst_bf[c*M + r] = src[r*ld + c], src MxN ----------------
__global__ void transpose_conv_kernel(const float* __restrict__ src, __nv_bfloat16* __restrict__ dst,
                                      int M, int N, int ld) {
    __shared__ float tile[32][33];
    int c0 = blockIdx.x * 32, r0 = blockIdx.y * 32;
    int c = c0 + threadIdx.x;
#pragma unroll
    for (int j = 0; j < 32; j += 8) {
        int r = r0 + threadIdx.y + j;
        tile[threadIdx.y + j][threadIdx.x] = src[(size_t)r * ld + c];
    }
    __syncthreads();
    int rr = r0 + threadIdx.x;
#pragma unroll
    for (int j = 0; j < 32; j += 8) {
        int cc = c0 + threadIdx.y + j;
        dst[(size_t)cc * M + rr] = __float2bfloat16(tile[threadIdx.x][threadIdx.y + j]);
    }
}

// ---------------- straight fp32 -> bf16 convert (n4 = elems/4) ----------------
__global__ void conv_bf_kernel(const float* __restrict__ src, __nv_bfloat16* __restrict__ dst, int n4) {
    int i = blockIdx.x * blockDim.x + threadIdx.x;
    if (i < n4) {
        float4 v = ((const float4*)src)[i];
        ((__nv_bfloat162*)dst)[i * 2]     = __floats2bfloat162_rn(v.x, v.y);
        ((__nv_bfloat162*)dst)[i * 2 + 1] = __floats2bfloat162_rn(v.z, v.w);
    }
}

// ---------------- extract + convert W_ih val columns ----------------
__global__ void conv_wihv_kernel(const float* __restrict__ Wih) {
    int j = blockIdx.x;
    for (int c = threadIdx.x; c < VALUE; c += blockDim.x)
        g_Wihv_bf[(size_t)j * VALUE + c] = __float2bfloat16(Wih[(size_t)j * LSTMIN + EMBD + c]);
}

// ------- tiled fp32 SGEMM: C[m][n] = sum_k A[m][k] * (BT ? B[n][k] : B[k][n]) + bias -------
template <bool BT>
__global__ __launch_bounds__(256) void sgemm_kernel(
    const float* __restrict__ A, int lda,
    const float* __restrict__ B, int ldb,
    float* __restrict__ C, int ldc, int K,
    const float* __restrict__ bias1, const float* __restrict__ bias2) {
    __shared__ float As[8][128];
    __shared__ float Bs[8][128];
    int m0 = blockIdx.y * 128, n0 = blockIdx.x * 128;
    int tid = threadIdx.x;
    int tx = tid & 15, ty = tid >> 4;
    int ar = tid >> 1, ac = (tid & 1) * 4;
    int bk = tid >> 5, bn = (tid & 31) * 4;
    float acc[8][8];
#pragma unroll
    for (int i = 0; i < 8; i++)
#pragma unroll
        for (int j = 0; j < 8; j++) acc[i][j] = 0.0f;

    for (int k0 = 0; k0 < K; k0 += 8) {
        float4 av = *(const float4*)(A + (size_t)(m0 + ar) * lda + k0 + ac);
        As[ac + 0][ar] = av.x; As[ac + 1][ar] = av.y;
        As[ac + 2][ar] = av.z; As[ac + 3][ar] = av.w;
        if (BT) {
            float4 bv = *(const float4*)(B + (size_t)(n0 + ar) * ldb + k0 + ac);
            Bs[ac + 0][ar] = bv.x; Bs[ac + 1][ar] = bv.y;
            Bs[ac + 2][ar] = bv.z; Bs[ac + 3][ar] = bv.w;
        } else {
            float4 bv = *(const float4*)(B + (size_t)(k0 + bk) * ldb + n0 + bn);
            *(float4*)&Bs[bk][bn] = bv;
        }
        __syncthreads();
#pragma unroll
        for (int kk = 0; kk < 8; kk++) {
            float4 ra0 = *(const float4*)&As[kk][ty * 8];
            float4 ra1 = *(const float4*)&As[kk][ty * 8 + 4];
            float4 rb0 = *(const float4*)&Bs[kk][tx * 8];
            float4 rb1 = *(const float4*)&Bs[kk][tx * 8 + 4];
            float ra[8] = {ra0.x, ra0.y, ra0.z, ra0.w, ra1.x, ra1.y, ra1.z, ra1.w};
            float rb[8] = {rb0.x, rb0.y, rb0.z, rb0.w, rb1.x, rb1.y, rb1.z, rb1.w};
#pragma unroll
            for (int i = 0; i < 8; i++)
#pragma unroll
                for (int j = 0; j < 8; j++) acc[i][j] += ra[i] * rb[j];
        }
        __syncthreads();
    }
#pragma unroll
    for (int i = 0; i < 8; i++) {
        int m = m0 + ty * 8 + i;
#pragma unroll
        for (int j = 0; j < 8; j++) {
            int n = n0 + tx * 8 + j;
            float b = bias1 ? bias1[n] : 0.0f;
            if (bias2) b += bias2[n];
            C[(size_t)m * ldc + n] = acc[i][j] + b;
        }
    }
}

// ---------------- persistent recurrent kernel (bf16 weights, fp32 state) ----------------
__global__ __launch_bounds__(NT, 1) void recurrent_kernel(
    const float* __restrict__ bq2) {
    __shared__ __align__(16) float sm[608];
    float* s_q   = sm;          // [256]  (stage 3)
    float* s_e   = sm + 256;    // [<=80] (stage 3)
    float* s_val = sm;          // [512]  (stage 5, reuse)
    float* s_go  = sm + 512;    // [16]   (stage 5)

    const int tid = threadIdx.x;
    const int warp = tid >> 5, lane = tid & 31;
    const int b = blockIdx.x;
    const int gw = b * 16 + warp;
    const int r0 = (b * NKB) / NB;
    const int r1 = ((b + 1) * NKB) / NB;

    unsigned tgt = g_gen + 1;

    for (int t = 0; t < SEQ; t++) {
        const float* hxo = (t & 1) ? g_hxB : g_hxA;
        float* hxn = (t & 1) ? g_hxA : g_hxB;

        // ---- S1: qh[j] = tanh(hx . Wq1T[j] + A1[t][j]) ; warp-per-output ----
        if (gw < QIN) {
            const uint4* w = (const uint4*)(g_Wq1T_bf + (size_t)gw * STATE); // 128 uint4
            const float4* h4 = (const float4*)hxo;
            float a = 0.0f;
#pragma unroll
            for (int i = 0; i < 4; i++) {
                int c = lane + 32 * i;
                a += bdot(w[c], h4[c * 2], h4[c * 2 + 1]);
            }
            a = wred(a);
            if (lane == 0) g_qh[gw] = tanhf(a + g_A1[(size_t)t * QIN + gw]);
        }
        grid_sync(tgt, b);

        // ---- S2: q[j] = qh . Wq2T[j] + bq2[j] ; warp-per-output ----
        if (gw < QUERY) {
            const uint4* w = (const uint4*)(g_Wq2T_bf + (size_t)gw * QIN);   // 256 uint4
            const float4* q4 = (const float4*)g_qh;
            float a = 0.0f;
#pragma unroll
            for (int i = 0; i < 8; i++) {
                int c = lane + 32 * i;
                a += bdot(w[c], q4[c * 2], q4[c * 2 + 1]);
            }
            a = wred(a);
            if (lane == 0) g_q[gw] = a + bq2[gw];
        }
        grid_sync(tgt, b);

        // ---- S3: per-block KB slice: scores -> exp -> partial val & z ----
        if (tid < QUERY) s_q[tid] = g_q[tid];
        __syncthreads();
        {
            const float4* q4 = (const float4*)s_q;
            for (int r = r0 + warp; r < r1; r += 16) {
                uint4 u = ((const uint4*)(g_kbk_bf + (size_t)r * QUERY))[lane]; // 32 uint4/row
                float a = bdot(u, q4[lane * 2], q4[lane * 2 + 1]);
                a = wred(a);
                if (lane == 0) s_e[r - r0] = expf(a);
            }
        }
        __syncthreads();
        {
            const int nl = r1 - r0;
            float a = 0.0f;
            const __nv_bfloat16* kv = g_kbv_bf + (size_t)r0 * VALUE + tid;
            for (int i = 0; i < nl; i++)
                a += s_e[i] * __bfloat162float(kv[(size_t)i * VALUE]);
            g_pval[(size_t)tid * 152 + b] = a;
            if (warp == 0) {
                float z = 0.0f;
                for (int i = lane; i < nl; i += 32) z += s_e[i];
                z = wred(z);
                if (lane == 0) g_pz[b] = z;
            }
        }
        grid_sync(tgt, b);

        // ---- S4: reduce partials -> val[512], invZ ----
        if (gw < VALUE) {
            float a = 0.0f;
#pragma unroll
            for (int i = 0; i < 5; i++) {
                int bb = lane + 32 * i;
                if (bb < NB) a += g_pval[(size_t)gw * 152 + bb];
            }
            a = wred(a);
            if (lane == 0) g_val[gw] = a;
        } else if (gw == VALUE) {
            float z = 0.0f;
#pragma unroll
            for (int i = 0; i < 5; i++) {
                int bb = lane + 32 * i;
                if (bb < NB) z += g_pz[bb];
            }
            z = wred(z);
            if (lane == 0) g_invZ = 1.0f / z;
        }
        grid_sync(tgt, b);

        // ---- S5: gates + LSTM update; idle blocks write output rows ----
        float invZ = g_invZ;
        if (b < 128) {
            if (tid < VALUE) s_val[tid] = g_val[tid] * invZ;
        } else if (b == 128) {
            if (tid < VALUE) g_dec_in[(size_t)t * DECIN + EMBD + tid] = g_val[tid] * invZ;
        } else if (b == 129) {
            for (int i = tid; i < STATE; i += NT)
                g_dec_in[(size_t)t * DECIN + EMBD + VALUE + i] = hxo[i];
        }
        __syncthreads();

        const int sl = warp >> 1;
        const int half = warp & 1;
        const int s = b * 8 + sl;
        float a0 = 0.0f, a1 = 0.0f;
        if (b < 128) {
            const int j0 = half * 2048 + s;   // half0: i | half1: g
            const int j1 = j0 + 1024;         // half0: f | half1: o
            const float4* v4 = (const float4*)s_val;
            const float4* h4 = (const float4*)hxo;
            const uint4* wv0 = (const uint4*)(g_Wihv_bf + (size_t)j0 * VALUE);  // 64 uint4
            const uint4* wv1 = (const uint4*)(g_Wihv_bf + (size_t)j1 * VALUE);
            const uint4* wh0 = (const uint4*)(g_Whh_bf + (size_t)j0 * STATE);   // 128 uint4
            const uint4* wh1 = (const uint4*)(g_Whh_bf + (size_t)j1 * STATE);
#pragma unroll
            for (int i = 0; i < 2; i++) {
                int c = lane + 32 * i;
                float4 va = v4[c * 2], vb = v4[c * 2 + 1];
                a0 += bdot(wv0[c], va, vb);
                a1 += bdot(wv1[c], va, vb);
            }
#pragma unroll
            for (int i = 0; i < 4; i++) {
                int c = lane + 32 * i;
                float4 ha = h4[c * 2], hb = h4[c * 2 + 1];
                a0 += bdot(wh0[c], ha, hb);
                a1 += bdot(wh1[c], ha, hb);
            }
            a0 = wred(a0); a1 = wred(a1);
            if (lane == 0) {
                a0 += g_Gx[(size_t)t * 4096 + j0];
                a1 += g_Gx[(size_t)t * 4096 + j1];
                if (half) { s_go[sl * 2] = a0; s_go[sl * 2 + 1] = a1; }
            }
        }
        __syncthreads();
        if (b < 128 && half == 0 && lane == 0) {
            float gg = s_go[sl * 2], oo = s_go[sl * 2 + 1];
            float c_old = g_cx[s];
            float cn = sigmoidf_(a1) * c_old + sigmoidf_(a0) * tanhf(gg);
            float hn = sigmoidf_(oo) * tanhf(cn);
            g_cx[s] = cn;
            hxn[s] = hn;
        }
        grid_sync(tgt, b);
    }
}

// ---------------- bf16 tensor-core decoder: C = A[2048,2560] @ B[32000,2560]^T ----------------
__global__ __launch_bounds__(256) void decoder_wmma_kernel(float* __restrict__ C) {
    __shared__ __nv_bfloat16 As[128][40];
    __shared__ __nv_bfloat16 Bs[128][40];
    const int m0 = blockIdx.y * 128, n0 = blockIdx.x * 128;
    const int tid = threadIdx.x;
    const int warp = tid >> 5;
    const int wm = warp >> 2, wn = warp & 3;   // 2 x 4 warps: warp tile 64 x 32
    const int lr = tid >> 2;                   // 0..63
    const int lc = (tid & 3) * 8;              // 0,8,16,24

    wmma::fragment<wmma::accumulator, 16, 16, 16, float> acc[4][2];
#pragma unroll
    for (int i = 0; i < 4; i++)
#pragma unroll
        for (int j = 0; j < 2; j++) wmma::fill_fragment(acc[i][j], 0.0f);

    for (int k0 = 0; k0 < DECIN; k0 += 32) {
        *(uint4*)&As[lr][lc]      = *(const uint4*)&g_dec_bf[(size_t)(m0 + lr) * DECIN + k0 + lc];
        *(uint4*)&As[lr + 64][lc] = *(const uint4*)&g_dec_bf[(size_t)(m0 + lr + 64) * DECIN + k0 + lc];
        *(uint4*)&Bs[lr][lc]      = *(const uint4*)&g_Wdec_bf[(size_t)(n0 + lr) * DECIN + k0 + lc];
        *(uint4*)&Bs[lr + 64][lc] = *(const uint4*)&g_Wdec_bf[(size_t)(n0 + lr + 64) * DECIN + k0 + lc];
        __syncthreads();
#pragma unroll
        for (int kk = 0; kk < 2; kk++) {
            wmma::fragment<wmma::matrix_a, 16, 16, 16, __nv_bfloat16, wmma::row_major> af[4];
            wmma::fragment<wmma::matrix_b, 16, 16, 16, __nv_bfloat16, wmma::col_major> bf[2];
#pragma unroll
            for (int i = 0; i < 4; i++)
                wmma::load_matrix_sync(af[i], &As[wm * 64 + i * 16][kk * 16], 40);
#pragma unroll
            for (int j = 0; j < 2; j++)
                wmma::load_matrix_sync(bf[j], &Bs[wn * 32 + j * 16][kk * 16], 40);
#pragma unroll
            for (int i = 0; i < 4; i++)
#pragma unroll
                for (int j = 0; j < 2; j++)
                    wmma::mma_sync(acc[i][j], af[i], bf[j], acc[i][j]);
        }
        __syncthreads();
    }
#pragma unroll
    for (int i = 0; i < 4; i++)
#pragma unroll
        for (int j = 0; j < 2; j++)
            wmma::store_matrix_sync(&C[(size_t)(m0 + wm * 64 + i * 16) * NTOK + n0 + wn * 32 + j * 16],
                                    acc[i][j], NTOK, wmma::mem_row_major);
}

// ---------------- row-wise log_softmax (folds in decoder bias) ----------------
__global__ __launch_bounds__(256) void logsoftmax_kernel(float* __restrict__ out,
                                                         const float* __restrict__ bias) {
    __shared__ float red[8];
    const int row = blockIdx.x;
    float* x = out + (size_t)row * NTOK;
    const int tid = threadIdx.x;

    float m = -1e30f;
    for (int i = tid; i < NTOK; i += 256) m = fmaxf(m, x[i] + bias[i]);
#pragma unroll
    for (int o = 16; o; o >>= 1) m = fmaxf(m, __shfl_xor_sync(0xffffffffu, m, o));
    if ((tid & 31) == 0) red[tid >> 5] = m;
    __syncthreads();
    float mm = red[0];
#pragma unroll
    for (int i = 1; i < 8; i++) mm = fmaxf(mm, red[i]);
    __syncthreads();

    float sum = 0.0f;
    for (int i = tid; i < NTOK; i += 256) sum += expf(x[i] + bias[i] - mm);
    sum = wred(sum);
    if ((tid & 31) == 0) red[tid >> 5] = sum;
    __syncthreads();
    float ss = 0.0f;
#pragma unroll
    for (int i = 0; i < 8; i++) ss += red[i];
    float lse = mm + logf(ss);

    for (int i = tid; i < NTOK; i += 256) x[i] = x[i] + bias[i] - lse;
}

// ---------------- launch ----------------
extern "C" void kernel_launch(void* const* d_in, const int* in_sizes, int n_in,
                              void* d_out, int out_size) {
    const int*   ids  = (const int*)d_in[0];
    const float* encW = (const float*)d_in[1];
    const float* Wq1  = (const float*)d_in[2];
    const float* bq1  = (const float*)d_in[3];
    const float* Wq2  = (const float*)d_in[4];
    const float* bq2  = (const float*)d_in[5];
    const float* kbk  = (const float*)d_in[6];
    const float* kbv  = (const float*)d_in[7];
    const float* Wih  = (const float*)d_in[8];
    const float* bih  = (const float*)d_in[9];
    const float* Whh  = (const float*)d_in[10];
    const float* bhh  = (const float*)d_in[11];
    const float* Wdec = (const float*)d_in[12];
    const float* bdec = (const float*)d_in[13];
    float* out = (float*)d_out;

    float *p_dec, *p_A1, *p_Gx;
    __nv_bfloat16 *p_Wq1T, *p_Wq2T, *p_kbk, *p_kbv, *p_Whh, *p_Wdec, *p_decbf;
    cudaGetSymbolAddress((void**)&p_dec,   g_dec_in);
    cudaGetSymbolAddress((void**)&p_A1,    g_A1);
    cudaGetSymbolAddress((void**)&p_Gx,    g_Gx);
    cudaGetSymbolAddress((void**)&p_Wq1T,  g_Wq1T_bf);
    cudaGetSymbolAddress((void**)&p_Wq2T,  g_Wq2T_bf);
    cudaGetSymbolAddress((void**)&p_kbk,   g_kbk_bf);
    cudaGetSymbolAddress((void**)&p_kbv,   g_kbv_bf);
    cudaGetSymbolAddress((void**)&p_Whh,   g_Whh_bf);
    cudaGetSymbolAddress((void**)&p_Wdec,  g_Wdec_bf);
    cudaGetSymbolAddress((void**)&p_decbf, g_dec_bf);

    dim3 tb(32, 8);
    embed_init_kernel<<<SEQ, 256>>>(ids, encW);
    // Wq1T_bf[j][k] = Wq1[k][j] (k < 1024 = hx rows)
    transpose_conv_kernel<<<dim3(QIN / 32, STATE / 32), tb>>>(Wq1, p_Wq1T, STATE, QIN, QIN);
    // Wq2T_bf[j][k] = Wq2[k][j]
    transpose_conv_kernel<<<dim3(QUERY / 32, QIN / 32), tb>>>(Wq2, p_Wq2T, QIN, QUERY, QUERY);
    conv_bf_kernel<<<(NKB * QUERY / 4 + 255) / 256, 256>>>(kbk, p_kbk, NKB * QUERY / 4);
    conv_bf_kernel<<<(NKB * VALUE / 4 + 255) / 256, 256>>>(kbv, p_kbv, NKB * VALUE / 4);
    conv_bf_kernel<<<(4 * STATE * STATE / 4 + 255) / 256, 256>>>(Whh, p_Whh, 4 * STATE * STATE / 4);
    conv_bf_kernel<<<(NTOK * DECIN / 4 + 255) / 256, 256>>>(Wdec, p_Wdec, NTOK * DECIN / 4);
    conv_wihv_kernel<<<4 * STATE, 256>>>(Wih);
    // A1 = emb @ Wq1[1024:, :] + bq1
    sgemm_kernel<false><<<dim3(QIN / 128, SEQ / 128), 256>>>(
        p_dec, DECIN, Wq1 + (size_t)STATE * QIN, QIN, p_A1, QIN, EMBD, bq1, nullptr);
    // Gx = emb @ W_ih[:, :1024]^T + b_ih + b_hh
    sgemm_kernel<true><<<dim3(4096 / 128, SEQ / 128), 256>>>(
        p_dec, DECIN, Wih, LSTMIN, p_Gx, 4096, EMBD, bih, bhh);
    // sequential recurrence (persistent, flag-array grid sync)
    recurrent_kernel<<<NB, NT>>>(bq2);
    // convert completed decoder input to bf16
    conv_bf_kernel<<<(SEQ * DECIN / 4 + 255) / 256, 256>>>(p_dec, p_decbf, SEQ * DECIN / 4);
    // decoder tensor-core GEMM + fused-bias log_softmax
    decoder_wmma_kernel<<<dim3(NTOK / 128, SEQ / 128), 256>>>(out);
    logsoftmax_kernel<<<SEQ, 256>>>(out, bdec);
}

// round 4
// speedup vs baseline: 1.4238x; 1.4238x over previous
#include <cuda_runtime.h>
#include <cuda_bf16.h>
#include <mma.h>
#include <math.h>

using namespace nvcuda;

#define SEQ     2048
#define EMBD    1024
#define STATE   1024
#define QIN     2048
#define QUERY   256
#define NKB     10000
#define VALUE   512
#define LSTMIN  1536
#define DECIN   2560
#define NTOK    32000
#define NB      148
#define NT      512

// ---------------- device scratch (no allocations allowed) ----------------
__device__ __align__(16) float g_dec_in[SEQ * DECIN];   // [emb | kb_out | lstm_states] fp32
__device__ __align__(16) __nv_bfloat16 g_dec_bf[SEQ * DECIN];
__device__ __align__(16) float g_A1[SEQ * QIN];
__device__ __align__(16) float g_Gx[SEQ * 4 * STATE];
__device__ __align__(16) __nv_bfloat16 g_Wq1T_bf[QIN * STATE];   // [2048 out][1024 k]
__device__ __align__(16) __nv_bfloat16 g_Wq2T_bf[QUERY * QIN];   // [256 out][2048 k]
__device__ __align__(16) __nv_bfloat16 g_kbk_bf[NKB * QUERY];
__device__ __align__(16) __nv_bfloat16 g_kbv_bf[NKB * VALUE];
__device__ __align__(16) __nv_bfloat16 g_Wihv_bf[4 * STATE * VALUE]; // W_ih[:,1024:1536]
__device__ __align__(16) __nv_bfloat16 g_Whh_bf[4 * STATE * STATE];
__device__ __align__(16) __nv_bfloat16 g_Wdec_bf[NTOK * DECIN];
__device__ __align__(16) float g_qh[QIN];
__device__ __align__(16) float g_q[QUERY];
__device__ __align__(16) float g_pval[VALUE * 152];
__device__ __align__(16) float g_pz[NB];
__device__ __align__(16) float g_val[VALUE];
__device__ float g_invZ;
__device__ __align__(16) float g_hxA[STATE];
__device__ __align__(16) float g_hxB[STATE];
__device__ __align__(16) float g_cx[STATE];
__device__ volatile unsigned g_gen;
__device__ unsigned g_cnt;

// ---------------- helpers ----------------
// 8 bf16 (as uint4) dotted with 8 fp32 (two float4)
__device__ __forceinline__ float bdot(uint4 u, float4 a, float4 b) {
    float2 p; float s;
    p = __bfloat1622float2(*(const __nv_bfloat162*)&u.x); s  = p.x * a.x + p.y * a.y;
    p = __bfloat1622float2(*(const __nv_bfloat162*)&u.y); s += p.x * a.z + p.y * a.w;
    p = __bfloat1622float2(*(const __nv_bfloat162*)&u.z); s += p.x * b.x + p.y * b.y;
    p = __bfloat1622float2(*(const __nv_bfloat162*)&u.w); s += p.x * b.z + p.y * b.w;
    return s;
}
__device__ __forceinline__ float sigmoidf_(float x) { return 1.0f / (1.0f + expf(-x)); }
__device__ __forceinline__ float wred(float a) {
#pragma unroll
    for (int o = 16; o; o >>= 1) a += __shfl_xor_sync(0xffffffffu, a, o);
    return a;
}

// R2-proven atomic grid barrier
__device__ __forceinline__ void grid_sync(unsigned &tgt) {
    __syncthreads();
    if (threadIdx.x == 0) {
        __threadfence();
        if (atomicAdd(&g_cnt, 1u) == NB - 1) {
            g_cnt = 0;
            __threadfence();
            g_gen = tgt;
        } else {
            while (g_gen != tgt) { }
        }
        __threadfence();
    }
    __syncthreads();
    tgt++;
}

// ---------------- launch 0: embedding gather + state init ----------------
__global__ void embed_init_kernel(const int* __restrict__ ids,
                                  const float* __restrict__ encW) {
    int t = blockIdx.x;
    int id = ids[t];
    for (int e = threadIdx.x; e < EMBD; e += blockDim.x)
        g_dec_in[(size_t)t * DECIN + e] = encW[(size_t)id * EMBD + e];
    if (blockIdx.x == 0) {
        for (int i = threadIdx.x; i < STATE; i += blockDim.x) {
            g_hxA[i] = 0.0f; g_hxB[i] = 0.0f; g_cx[i] = 0.0f;
        }
    }
}

// ---------------- launch 1: all straight fp32->bf16 conversions, fused ----------------
#define N4_KBK  (NKB * QUERY / 4)
#define N4_KBV  (NKB * VALUE / 4)
#define N4_WHH  (4 * STATE * STATE / 4)
#define N4_WDEC (NTOK * DECIN / 4)
#define N4_WIHV (4 * STATE * VALUE / 4)
#define N4_TOT  (N4_KBK + N4_KBV + N4_WHH + N4_WDEC + N4_WIHV)

__device__ __forceinline__ void conv4(const float* __restrict__ s, __nv_bfloat16* d, long i) {
    float4 v = ((const float4*)s)[i];
    ((__nv_bfloat162*)d)[i * 2]     = __floats2bfloat162_rn(v.x, v.y);
    ((__nv_bfloat162*)d)[i * 2 + 1] = __floats2bfloat162_rn(v.z, v.w);
}

__global__ void conv_all_kernel(const float* __restrict__ kbk, const float* __restrict__ kbv,
                                const float* __restrict__ Whh, const float* __restrict__ Wdec,
                                const float* __restrict__ Wih) {
    long i = (long)blockIdx.x * blockDim.x + threadIdx.x;
    if (i < N4_KBK) { conv4(kbk, g_kbk_bf, i); return; }
    i -= N4_KBK;
    if (i < N4_KBV) { conv4(kbv, g_kbv_bf, i); return; }
    i -= N4_KBV;
    if (i < N4_WHH) { conv4(Whh, g_Whh_bf, i); return; }
    i -= N4_WHH;
    if (i < N4_WDEC) { conv4(Wdec, g_Wdec_bf, i); return; }
    i -= N4_WDEC;
    if (i < N4_WIHV) {
        long row = i >> 7, col = (i & 127);   // 128 float4 per row
        float4 v = *(const float4*)(Wih + row * LSTMIN + EMBD + col * 4);
        ((__nv_bfloat162*)g_Wihv_bf)[i * 2]     = __floats2bfloat162_rn(v.x, v.y);
        ((__nv_bfloat162*)g_Wihv_bf)[i * 2 + 1] = __floats2bfloat162_rn(v.z, v.w);
    }
}

// ---------------- launch 2: both transposes fused ----------------
// grid (64, 40): by<32 -> Wq1T (src STATE x QIN), by>=32 -> Wq2T (src QIN x QUERY, bx=r-blk, by-32=c-blk)
__global__ void transpose_both_kernel(const float* __restrict__ Wq1, const float* __restrict__ Wq2) {
    __shared__ float tile[32][33];
    const float* src; __nv_bfloat16* dst; int M, ld, c0, r0;
    if (blockIdx.y < 32) { src = Wq1; dst = g_Wq1T_bf; M = STATE; ld = QIN;
                           c0 = blockIdx.x * 32; r0 = blockIdx.y * 32; }
    else                 { src = Wq2; dst = g_Wq2T_bf; M = QIN; ld = QUERY;
                           c0 = (blockIdx.y - 32) * 32; r0 = blockIdx.x * 32; }
#pragma unroll
    for (int j = 0; j < 32; j += 8) {
        int r = r0 + threadIdx.y + j;
        tile[threadIdx.y + j][threadIdx.x] = src[(size_t)r * ld + c0 + threadIdx.x];
    }
    __syncthreads();
    int rr = r0 + threadIdx.x;
#pragma unroll
    for (int j = 0; j < 32; j += 8) {
        int cc = c0 + threadIdx.y + j;
        dst[(size_t)cc * M + rr] = __float2bfloat16(tile[threadIdx.x][threadIdx.y + j]);
    }
}

// ------- launches 3,4: tiled fp32 SGEMM (prolog only) -------
template <bool BT>
__global__ __launch_bounds__(256) void sgemm_kernel(
    const float* __restrict__ A, int lda,
    const float* __restrict__ B, int ldb,
    float* __restrict__ C, int ldc, int K,
    const float* __restrict__ bias1, const float* __restrict__ bias2) {
    __shared__ float As[8][128];
    __shared__ float Bs[8][128];
    int m0 = blockIdx.y * 128, n0 = blockIdx.x * 128;
    int tid = threadIdx.x;
    int tx = tid & 15, ty = tid >> 4;
    int ar = tid >> 1, ac = (tid & 1) * 4;
    int bk = tid >> 5, bn = (tid & 31) * 4;
    float acc[8][8];
#pragma unroll
    for (int i = 0; i < 8; i++)
#pragma unroll
        for (int j = 0; j < 8; j++) acc[i][j] = 0.0f;

    for (int k0 = 0; k0 < K; k0 += 8) {
        float4 av = *(const float4*)(A + (size_t)(m0 + ar) * lda + k0 + ac);
        As[ac + 0][ar] = av.x; As[ac + 1][ar] = av.y;
        As[ac + 2][ar] = av.z; As[ac + 3][ar] = av.w;
        if (BT) {
            float4 bv = *(const float4*)(B + (size_t)(n0 + ar) * ldb + k0 + ac);
            Bs[ac + 0][ar] = bv.x; Bs[ac + 1][ar] = bv.y;
            Bs[ac + 2][ar] = bv.z; Bs[ac + 3][ar] = bv.w;
        } else {
            float4 bv = *(const float4*)(B + (size_t)(k0 + bk) * ldb + n0 + bn);
            *(float4*)&Bs[bk][bn] = bv;
        }
        __syncthreads();
#pragma unroll
        for (int kk = 0; kk < 8; kk++) {
            float4 ra0 = *(const float4*)&As[kk][ty * 8];
            float4 ra1 = *(const float4*)&As[kk][ty * 8 + 4];
            float4 rb0 = *(const float4*)&Bs[kk][tx * 8];
            float4 rb1 = *(const float4*)&Bs[kk][tx * 8 + 4];
            float ra[8] = {ra0.x, ra0.y, ra0.z, ra0.w, ra1.x, ra1.y, ra1.z, ra1.w};
            float rb[8] = {rb0.x, rb0.y, rb0.z, rb0.w, rb1.x, rb1.y, rb1.z, rb1.w};
#pragma unroll
            for (int i = 0; i < 8; i++)
#pragma unroll
                for (int j = 0; j < 8; j++) acc[i][j] += ra[i] * rb[j];
        }
        __syncthreads();
    }
#pragma unroll
    for (int i = 0; i < 8; i++) {
        int m = m0 + ty * 8 + i;
#pragma unroll
        for (int j = 0; j < 8; j++) {
            int n = n0 + tx * 8 + j;
            float b = bias1 ? bias1[n] : 0.0f;
            if (bias2) b += bias2[n];
            C[(size_t)m * ldc + n] = acc[i][j] + b;
        }
    }
}

// ---------------- launch 5 (ncu -s 5 slot): persistent recurrent kernel ----------------
__global__ __launch_bounds__(NT, 1) void recurrent_kernel(
    const float* __restrict__ bq2) {
    __shared__ __align__(16) float sm[608];
    float* s_q   = sm;          // [256]  (stage 3)
    float* s_e   = sm + 256;    // [<=80] (stage 3)
    float* s_val = sm;          // [512]  (stage 5, reuse)
    float* s_go  = sm + 512;    // [16]   (stage 5)

    const int tid = threadIdx.x;
    const int warp = tid >> 5, lane = tid & 31;
    const int b = blockIdx.x;
    const int gw = b * 16 + warp;
    const int r0 = (b * NKB) / NB;
    const int r1 = ((b + 1) * NKB) / NB;

    unsigned tgt = g_gen + 1;

    for (int t = 0; t < SEQ; t++) {
        const float* hxo = (t & 1) ? g_hxB : g_hxA;
        float* hxn = (t & 1) ? g_hxA : g_hxB;

        // ---- S1: qh[j] = tanh(hx . Wq1T[j] + A1[t][j]) ; warp-per-output ----
        if (gw < QIN) {
            const uint4* w = (const uint4*)(g_Wq1T_bf + (size_t)gw * STATE); // 128 uint4
            const float4* h4 = (const float4*)hxo;
            float a = 0.0f;
#pragma unroll
            for (int i = 0; i < 4; i++) {
                int c = lane + 32 * i;
                a += bdot(w[c], h4[c * 2], h4[c * 2 + 1]);
            }
            a = wred(a);
            if (lane == 0) g_qh[gw] = tanhf(a + g_A1[(size_t)t * QIN + gw]);
        }
        grid_sync(tgt);

        // ---- S2: q[j] = qh . Wq2T[j] + bq2[j] ; warp-per-output ----
        if (gw < QUERY) {
            const uint4* w = (const uint4*)(g_Wq2T_bf + (size_t)gw * QIN);   // 256 uint4
            const float4* q4 = (const float4*)g_qh;
            float a = 0.0f;
#pragma unroll
            for (int i = 0; i < 8; i++) {
                int c = lane + 32 * i;
                a += bdot(w[c], q4[c * 2], q4[c * 2 + 1]);
            }
            a = wred(a);
            if (lane == 0) g_q[gw] = a + bq2[gw];
        }
        grid_sync(tgt);

        // ---- S3: per-block KB slice: scores -> exp -> partial val & z ----
        if (tid < QUERY) s_q[tid] = g_q[tid];
        __syncthreads();
        {
            const float4* q4 = (const float4*)s_q;
            for (int r = r0 + warp; r < r1; r += 16) {
                uint4 u = ((const uint4*)(g_kbk_bf + (size_t)r * QUERY))[lane]; // 32 uint4/row
                float a = bdot(u, q4[lane * 2], q4[lane * 2 + 1]);
                a = wred(a);
                if (lane == 0) s_e[r - r0] = expf(a);
            }
        }
        __syncthreads();
        {
            const int nl = r1 - r0;
            float a = 0.0f;
            const __nv_bfloat16* kv = g_kbv_bf + (size_t)r0 * VALUE + tid;
            for (int i = 0; i < nl; i++)
                a += s_e[i] * __bfloat162float(kv[(size_t)i * VALUE]);
            g_pval[(size_t)tid * 152 + b] = a;
            if (warp == 0) {
                float z = 0.0f;
                for (int i = lane; i < nl; i += 32) z += s_e[i];
                z = wred(z);
                if (lane == 0) g_pz[b] = z;
            }
        }
        grid_sync(tgt);

        // ---- S4: reduce partials -> val[512], invZ ----
        if (gw < VALUE) {
            float a = 0.0f;
#pragma unroll
            for (int i = 0; i < 5; i++) {
                int bb = lane + 32 * i;
                if (bb < NB) a += g_pval[(size_t)gw * 152 + bb];
            }
            a = wred(a);
            if (lane == 0) g_val[gw] = a;
        } else if (gw == VALUE) {
            float z = 0.0f;
#pragma unroll
            for (int i = 0; i < 5; i++) {
                int bb = lane + 32 * i;
                if (bb < NB) z += g_pz[bb];
            }
            z = wred(z);
            if (lane == 0) g_invZ = 1.0f / z;
        }
        grid_sync(tgt);

        // ---- S5: gates + LSTM update; idle blocks write output rows ----
        float invZ = g_invZ;
        if (b < 128) {
            if (tid < VALUE) s_val[tid] = g_val[tid] * invZ;
        } else if (b == 128) {
            if (tid < VALUE) g_dec_in[(size_t)t * DECIN + EMBD + tid] = g_val[tid] * invZ;
        } else if (b == 129) {
            for (int i = tid; i < STATE; i += NT)
                g_dec_in[(size_t)t * DECIN + EMBD + VALUE + i] = hxo[i];
        }
        __syncthreads();

        const int sl = warp >> 1;
        const int half = warp & 1;
        const int s = b * 8 + sl;
        float a0 = 0.0f, a1 = 0.0f;
        if (b < 128) {
            const int j0 = half * 2048 + s;   // half0: i | half1: g
            const int j1 = j0 + 1024;         // half0: f | half1: o
            const float4* v4 = (const float4*)s_val;
            const float4* h4 = (const float4*)hxo;
            const uint4* wv0 = (const uint4*)(g_Wihv_bf + (size_t)j0 * VALUE);  // 64 uint4
            const uint4* wv1 = (const uint4*)(g_Wihv_bf + (size_t)j1 * VALUE);
            const uint4* wh0 = (const uint4*)(g_Whh_bf + (size_t)j0 * STATE);   // 128 uint4
            const uint4* wh1 = (const uint4*)(g_Whh_bf + (size_t)j1 * STATE);
#pragma unroll
            for (int i = 0; i < 2; i++) {
                int c = lane + 32 * i;
                float4 va = v4[c * 2], vb = v4[c * 2 + 1];
                a0 += bdot(wv0[c], va, vb);
                a1 += bdot(wv1[c], va, vb);
            }
#pragma unroll
            for (int i = 0; i < 4; i++) {
                int c = lane + 32 * i;
                float4 ha = h4[c * 2], hb = h4[c * 2 + 1];
                a0 += bdot(wh0[c], ha, hb);
                a1 += bdot(wh1[c], ha, hb);
            }
            a0 = wred(a0); a1 = wred(a1);
            if (lane == 0) {
                a0 += g_Gx[(size_t)t * 4096 + j0];
                a1 += g_Gx[(size_t)t * 4096 + j1];
                if (half) { s_go[sl * 2] = a0; s_go[sl * 2 + 1] = a1; }
            }
        }
        __syncthreads();
        if (b < 128 && half == 0 && lane == 0) {
            float gg = s_go[sl * 2], oo = s_go[sl * 2 + 1];
            float c_old = g_cx[s];
            float cn = sigmoidf_(a1) * c_old + sigmoidf_(a0) * tanhf(gg);
            float hn = sigmoidf_(oo) * tanhf(cn);
            g_cx[s] = cn;
            hxn[s] = hn;
        }
        grid_sync(tgt);
    }
}

// ---------------- launch 6: dec_in -> bf16 ----------------
__global__ void conv_dec_kernel() {
    int i = blockIdx.x * blockDim.x + threadIdx.x;  // float4 index
    if (i < SEQ * DECIN / 4) {
        float4 v = ((const float4*)g_dec_in)[i];
        ((__nv_bfloat162*)g_dec_bf)[i * 2]     = __floats2bfloat162_rn(v.x, v.y);
        ((__nv_bfloat162*)g_dec_bf)[i * 2 + 1] = __floats2bfloat162_rn(v.z, v.w);
    }
}

// ---------------- launch 7: bf16 tensor-core decoder: C = A[2048,2560] @ B[32000,2560]^T ----------------
__global__ __launch_bounds__(256) void decoder_wmma_kernel(float* __restrict__ C) {
    __shared__ __nv_bfloat16 As[128][40];
    __shared__ __nv_bfloat16 Bs[128][40];
    const int m0 = blockIdx.y * 128, n0 = blockIdx.x * 128;
    const int tid = threadIdx.x;
    const int warp = tid >> 5;
    const int wm = warp >> 2, wn = warp & 3;   // 2 x 4 warps: warp tile 64 x 32
    const int lr = tid >> 2;                   // 0..63
    const int lc = (tid & 3) * 8;              // 0,8,16,24

    wmma::fragment<wmma::accumulator, 16, 16, 16, float> acc[4][2];
#pragma unroll
    for (int i = 0; i < 4; i++)
#pragma unroll
        for (int j = 0; j < 2; j++) wmma::fill_fragment(acc[i][j], 0.0f);

    for (int k0 = 0; k0 < DECIN; k0 += 32) {
        *(uint4*)&As[lr][lc]      = *(const uint4*)&g_dec_bf[(size_t)(m0 + lr) * DECIN + k0 + lc];
        *(uint4*)&As[lr + 64][lc] = *(const uint4*)&g_dec_bf[(size_t)(m0 + lr + 64) * DECIN + k0 + lc];
        *(uint4*)&Bs[lr][lc]      = *(const uint4*)&g_Wdec_bf[(size_t)(n0 + lr) * DECIN + k0 + lc];
        *(uint4*)&Bs[lr + 64][lc] = *(const uint4*)&g_Wdec_bf[(size_t)(n0 + lr + 64) * DECIN + k0 + lc];
        __syncthreads();
#pragma unroll
        for (int kk = 0; kk < 2; kk++) {
            wmma::fragment<wmma::matrix_a, 16, 16, 16, __nv_bfloat16, wmma::row_major> af[4];
            wmma::fragment<wmma::matrix_b, 16, 16, 16, __nv_bfloat16, wmma::col_major> bf[2];
#pragma unroll
            for (int i = 0; i < 4; i++)
                wmma::load_matrix_sync(af[i], &As[wm * 64 + i * 16][kk * 16], 40);
#pragma unroll
            for (int j = 0; j < 2; j++)
                wmma::load_matrix_sync(bf[j], &Bs[wn * 32 + j * 16][kk * 16], 40);
#pragma unroll
            for (int i = 0; i < 4; i++)
#pragma unroll
                for (int j = 0; j < 2; j++)
                    wmma::mma_sync(acc[i][j], af[i], bf[j], acc[i][j]);
        }
        __syncthreads();
    }
#pragma unroll
    for (int i = 0; i < 4; i++)
#pragma unroll
        for (int j = 0; j < 2; j++)
            wmma::store_matrix_sync(&C[(size_t)(m0 + wm * 64 + i * 16) * NTOK + n0 + wn * 32 + j * 16],
                                    acc[i][j], NTOK, wmma::mem_row_major);
}

// ---------------- launch 8: row-wise log_softmax (folds in decoder bias) ----------------
__global__ __launch_bounds__(256) void logsoftmax_kernel(float* __restrict__ out,
                                                         const float* __restrict__ bias) {
    __shared__ float red[8];
    const int row = blockIdx.x;
    float* x = out + (size_t)row * NTOK;
    const int tid = threadIdx.x;

    float m = -1e30f;
    for (int i = tid; i < NTOK; i += 256) m = fmaxf(m, x[i] + bias[i]);
#pragma unroll
    for (int o = 16; o; o >>= 1) m = fmaxf(m, __shfl_xor_sync(0xffffffffu, m, o));
    if ((tid & 31) == 0) red[tid >> 5] = m;
    __syncthreads();
    float mm = red[0];
#pragma unroll
    for (int i = 1; i < 8; i++) mm = fmaxf(mm, red[i]);
    __syncthreads();

    float sum = 0.0f;
    for (int i = tid; i < NTOK; i += 256) sum += expf(x[i] + bias[i] - mm);
    sum = wred(sum);
    if ((tid & 31) == 0) red[tid >> 5] = sum;
    __syncthreads();
    float ss = 0.0f;
#pragma unroll
    for (int i = 0; i < 8; i++) ss += red[i];
    float lse = mm + logf(ss);

    for (int i = tid; i < NTOK; i += 256) x[i] = x[i] + bias[i] - lse;
}

// ---------------- launch ----------------
extern "C" void kernel_launch(void* const* d_in, const int* in_sizes, int n_in,
                              void* d_out, int out_size) {
    const int*   ids  = (const int*)d_in[0];
    const float* encW = (const float*)d_in[1];
    const float* Wq1  = (const float*)d_in[2];
    const float* bq1  = (const float*)d_in[3];
    const float* Wq2  = (const float*)d_in[4];
    const float* bq2  = (const float*)d_in[5];
    const float* kbk  = (const float*)d_in[6];
    const float* kbv  = (const float*)d_in[7];
    const float* Wih  = (const float*)d_in[8];
    const float* bih  = (const float*)d_in[9];
    const float* Whh  = (const float*)d_in[10];
    const float* bhh  = (const float*)d_in[11];
    const float* Wdec = (const float*)d_in[12];
    const float* bdec = (const float*)d_in[13];
    float* out = (float*)d_out;

    float *p_dec, *p_A1, *p_Gx;
    cudaGetSymbolAddress((void**)&p_dec, g_dec_in);
    cudaGetSymbolAddress((void**)&p_A1,  g_A1);
    cudaGetSymbolAddress((void**)&p_Gx,  g_Gx);

    // launch 0
    embed_init_kernel<<<SEQ, 256>>>(ids, encW);
    // launch 1: all bf16 conversions fused
    conv_all_kernel<<<(N4_TOT + 255) / 256, 256>>>(kbk, kbv, Whh, Wdec, Wih);
    // launch 2: both transposes
    transpose_both_kernel<<<dim3(64, 40), dim3(32, 8)>>>(Wq1, Wq2);
    // launch 3: A1 = emb @ Wq1[1024:, :] + bq1
    sgemm_kernel<false><<<dim3(QIN / 128, SEQ / 128), 256>>>(
        p_dec, DECIN, Wq1 + (size_t)STATE * QIN, QIN, p_A1, QIN, EMBD, bq1, nullptr);
    // launch 4: Gx = emb @ W_ih[:, :1024]^T + b_ih + b_hh
    sgemm_kernel<true><<<dim3(4096 / 128, SEQ / 128), 256>>>(
        p_dec, DECIN, Wih, LSTMIN, p_Gx, 4096, EMBD, bih, bhh);
    // launch 5 (ncu -s 5 profiles this): sequential recurrence
    recurrent_kernel<<<NB, NT>>>(bq2);
    // launch 6: convert decoder input to bf16
    conv_dec_kernel<<<(SEQ * DECIN / 4 + 255) / 256, 256>>>();
    // launch 7: decoder tensor-core GEMM
    decoder_wmma_kernel<<<dim3(NTOK / 128, SEQ / 128), 256>>>(out);
    // launch 8: fused-bias log_softmax
    logsoftmax_kernel<<<SEQ, 256>>>(out, bdec);
}

// round 5
// speedup vs baseline: 1.6309x; 1.1454x over previous
#include <cuda_runtime.h>
#include <cuda_bf16.h>
#include <mma.h>
#include <math.h>

using namespace nvcuda;

#define SEQ     2048
#define EMBD    1024
#define STATE   1024
#define QIN     2048
#define QUERY   256
#define NKB     10000
#define VALUE   512
#define LSTMIN  1536
#define DECIN   2560
#define NTOK    32000
#define NB      148
#define NT      512

// ---------------- device scratch (no allocations allowed) ----------------
__device__ __align__(16) float g_dec_in[SEQ * DECIN];   // [emb | kb_out | lstm_states] fp32
__device__ __align__(16) __nv_bfloat16 g_dec_bf[SEQ * DECIN];
__device__ __align__(16) float g_A1[SEQ * QIN];
__device__ __align__(16) float g_Gx[SEQ * 4 * STATE];
__device__ __align__(16) __nv_bfloat16 g_Wq1T_bf[QIN * STATE];   // [2048 out][1024 k]
__device__ __align__(16) __nv_bfloat16 g_kbk_bf[NKB * QUERY];
__device__ __align__(16) __nv_bfloat16 g_kbv_bf[NKB * VALUE];
__device__ __align__(16) __nv_bfloat16 g_Wihv_bf[4 * STATE * VALUE]; // W_ih[:,1024:1536]
__device__ __align__(16) __nv_bfloat16 g_Whh_bf[4 * STATE * STATE];
__device__ __align__(16) __nv_bfloat16 g_Wdec_bf[NTOK * DECIN];
__device__ __align__(16) float g_q[QUERY];     // atomic-accumulated
__device__ __align__(16) float g_val[VALUE];   // atomic-accumulated
__device__ float g_z;                          // atomic-accumulated
__device__ __align__(16) float g_hxA[STATE];
__device__ __align__(16) float g_hxB[STATE];
__device__ __align__(16) float g_cx[STATE];
// tree barrier state (monotonic u64 counters: no reset race)
__device__ unsigned long long g_leaf[8 * 16];  // stride 16 ull = 128B (own L2 line each)
__device__ unsigned long long g_root;
__device__ volatile unsigned long long g_gen;

// ---------------- helpers ----------------
// 8 bf16 (as uint4) dotted with 8 fp32 (two float4)
__device__ __forceinline__ float bdot(uint4 u, float4 a, float4 b) {
    float2 p; float s;
    p = __bfloat1622float2(*(const __nv_bfloat162*)&u.x); s  = p.x * a.x + p.y * a.y;
    p = __bfloat1622float2(*(const __nv_bfloat162*)&u.y); s += p.x * a.z + p.y * a.w;
    p = __bfloat1622float2(*(const __nv_bfloat162*)&u.z); s += p.x * b.x + p.y * b.y;
    p = __bfloat1622float2(*(const __nv_bfloat162*)&u.w); s += p.x * b.z + p.y * b.w;
    return s;
}
__device__ __forceinline__ float sigmoidf_(float x) { return 1.0f / (1.0f + expf(-x)); }
__device__ __forceinline__ float wred(float a) {
#pragma unroll
    for (int o = 16; o; o >>= 1) a += __shfl_xor_sync(0xffffffffu, a, o);
    return a;
}

// tree grid barrier: 8 leaves (<=19 arrivals each, parallel L2 lines) + root (8)
__device__ __forceinline__ void grid_sync(unsigned long long &tgt, int b) {
    __syncthreads();
    if (threadIdx.x == 0) {
        __threadfence();
        const int grp = b & 7;
        const unsigned long long cnt = 18ull + ((grp < 4) ? 1ull : 0ull);
        if (atomicAdd(&g_leaf[grp * 16], 1ull) + 1ull == cnt * tgt) {
            if (atomicAdd(&g_root, 1ull) + 1ull == 8ull * tgt) {
                __threadfence();
                g_gen = tgt;
            }
        }
        while (g_gen != tgt) { }
        __threadfence();
    }
    __syncthreads();
    tgt++;
}

// ---------------- launch 0: embedding gather + state init ----------------
__global__ void embed_init_kernel(const int* __restrict__ ids,
                                  const float* __restrict__ encW) {
    int t = blockIdx.x;
    int id = ids[t];
    for (int e = threadIdx.x; e < EMBD; e += blockDim.x)
        g_dec_in[(size_t)t * DECIN + e] = encW[(size_t)id * EMBD + e];
    if (blockIdx.x == 0) {
        for (int i = threadIdx.x; i < STATE; i += blockDim.x) {
            g_hxA[i] = 0.0f; g_hxB[i] = 0.0f; g_cx[i] = 0.0f;
        }
        for (int i = threadIdx.x; i < VALUE; i += blockDim.x) g_val[i] = 0.0f;
        if (threadIdx.x < QUERY) g_q[threadIdx.x] = 0.0f;
        if (threadIdx.x == 0) g_z = 0.0f;
    }
}

// ---------------- launch 1: all straight fp32->bf16 conversions, fused ----------------
#define N4_KBK  (NKB * QUERY / 4)
#define N4_KBV  (NKB * VALUE / 4)
#define N4_WHH  (4 * STATE * STATE / 4)
#define N4_WDEC (NTOK * DECIN / 4)
#define N4_WIHV (4 * STATE * VALUE / 4)
#define N4_TOT  (N4_KBK + N4_KBV + N4_WHH + N4_WDEC + N4_WIHV)

__device__ __forceinline__ void conv4(const float* __restrict__ s, __nv_bfloat16* d, long i) {
    float4 v = ((const float4*)s)[i];
    ((__nv_bfloat162*)d)[i * 2]     = __floats2bfloat162_rn(v.x, v.y);
    ((__nv_bfloat162*)d)[i * 2 + 1] = __floats2bfloat162_rn(v.z, v.w);
}

__global__ void conv_all_kernel(const float* __restrict__ kbk, const float* __restrict__ kbv,
                                const float* __restrict__ Whh, const float* __restrict__ Wdec,
                                const float* __restrict__ Wih) {
    long i = (long)blockIdx.x * blockDim.x + threadIdx.x;
    if (i < N4_KBK) { conv4(kbk, g_kbk_bf, i); return; }
    i -= N4_KBK;
    if (i < N4_KBV) { conv4(kbv, g_kbv_bf, i); return; }
    i -= N4_KBV;
    if (i < N4_WHH) { conv4(Whh, g_Whh_bf, i); return; }
    i -= N4_WHH;
    if (i < N4_WDEC) { conv4(Wdec, g_Wdec_bf, i); return; }
    i -= N4_WDEC;
    if (i < N4_WIHV) {
        long row = i >> 7, col = (i & 127);   // 128 float4 per row
        float4 v = *(const float4*)(Wih + row * LSTMIN + EMBD + col * 4);
        ((__nv_bfloat162*)g_Wihv_bf)[i * 2]     = __floats2bfloat162_rn(v.x, v.y);
        ((__nv_bfloat162*)g_Wihv_bf)[i * 2 + 1] = __floats2bfloat162_rn(v.z, v.w);
    }
}

// ---------------- launch 2: Wq1 (hx rows) transpose -> bf16 ----------------
__global__ void transpose_wq1_kernel(const float* __restrict__ Wq1) {
    __shared__ float tile[32][33];
    int c0 = blockIdx.x * 32, r0 = blockIdx.y * 32;   // c over QIN, r over STATE
#pragma unroll
    for (int j = 0; j < 32; j += 8) {
        int r = r0 + threadIdx.y + j;
        tile[threadIdx.y + j][threadIdx.x] = Wq1[(size_t)r * QIN + c0 + threadIdx.x];
    }
    __syncthreads();
    int rr = r0 + threadIdx.x;
#pragma unroll
    for (int j = 0; j < 32; j += 8) {
        int cc = c0 + threadIdx.y + j;
        g_Wq1T_bf[(size_t)cc * STATE + rr] = __float2bfloat16(tile[threadIdx.x][threadIdx.y + j]);
    }
}

// ------- launches 3,4: tiled fp32 SGEMM (prolog only) -------
template <bool BT>
__global__ __launch_bounds__(256) void sgemm_kernel(
    const float* __restrict__ A, int lda,
    const float* __restrict__ B, int ldb,
    float* __restrict__ C, int ldc, int K,
    const float* __restrict__ bias1, const float* __restrict__ bias2) {
    __shared__ float As[8][128];
    __shared__ float Bs[8][128];
    int m0 = blockIdx.y * 128, n0 = blockIdx.x * 128;
    int tid = threadIdx.x;
    int tx = tid & 15, ty = tid >> 4;
    int ar = tid >> 1, ac = (tid & 1) * 4;
    int bk = tid >> 5, bn = (tid & 31) * 4;
    float acc[8][8];
#pragma unroll
    for (int i = 0; i < 8; i++)
#pragma unroll
        for (int j = 0; j < 8; j++) acc[i][j] = 0.0f;

    for (int k0 = 0; k0 < K; k0 += 8) {
        float4 av = *(const float4*)(A + (size_t)(m0 + ar) * lda + k0 + ac);
        As[ac + 0][ar] = av.x; As[ac + 1][ar] = av.y;
        As[ac + 2][ar] = av.z; As[ac + 3][ar] = av.w;
        if (BT) {
            float4 bv = *(const float4*)(B + (size_t)(n0 + ar) * ldb + k0 + ac);
            Bs[ac + 0][ar] = bv.x; Bs[ac + 1][ar] = bv.y;
            Bs[ac + 2][ar] = bv.z; Bs[ac + 3][ar] = bv.w;
        } else {
            float4 bv = *(const float4*)(B + (size_t)(k0 + bk) * ldb + n0 + bn);
            *(float4*)&Bs[bk][bn] = bv;
        }
        __syncthreads();
#pragma unroll
        for (int kk = 0; kk < 8; kk++) {
            float4 ra0 = *(const float4*)&As[kk][ty * 8];
            float4 ra1 = *(const float4*)&As[kk][ty * 8 + 4];
            float4 rb0 = *(const float4*)&Bs[kk][tx * 8];
            float4 rb1 = *(const float4*)&Bs[kk][tx * 8 + 4];
            float ra[8] = {ra0.x, ra0.y, ra0.z, ra0.w, ra1.x, ra1.y, ra1.z, ra1.w};
            float rb[8] = {rb0.x, rb0.y, rb0.z, rb0.w, rb1.x, rb1.y, rb1.z, rb1.w};
#pragma unroll
            for (int i = 0; i < 8; i++)
#pragma unroll
                for (int j = 0; j < 8; j++) acc[i][j] += ra[i] * rb[j];
        }
        __syncthreads();
    }
#pragma unroll
    for (int i = 0; i < 8; i++) {
        int m = m0 + ty * 8 + i;
#pragma unroll
        for (int j = 0; j < 8; j++) {
            int n = n0 + tx * 8 + j;
            float b = bias1 ? bias1[n] : 0.0f;
            if (bias2) b += bias2[n];
            C[(size_t)m * ldc + n] = acc[i][j] + b;
        }
    }
}

// ---------------- launch 5: persistent recurrent kernel (3 barriers/step) ----------------
__global__ __launch_bounds__(NT, 1) void recurrent_kernel(
    const float* __restrict__ Wq2, const float* __restrict__ bq2) {
    __shared__ __align__(16) float sm[608];
    float* s_q   = sm;          // [256]  (SB)
    float* s_e   = sm + 256;    // [<=80] (SB)
    float* s_val = sm;          // [512]  (SC, reuse)
    float* s_go  = sm + 512;    // [16]   (SC)
    float* s_qh  = sm + 528;    // [16]   (SA)

    const int tid = threadIdx.x;
    const int warp = tid >> 5, lane = tid & 31;
    const int b = blockIdx.x;
    const int r0 = (b * NKB) / NB;
    const int r1 = ((b + 1) * NKB) / NB;
    const int k0 = (b * QIN) / NB;
    const int nk = ((b + 1) * QIN) / NB - k0;   // 13 or 14

    unsigned long long tgt = g_gen + 1;

    for (int t = 0; t < SEQ; t++) {
        const float* hxo = (t & 1) ? g_hxB : g_hxA;
        float* hxn = (t & 1) ? g_hxA : g_hxB;

        // ---- SA: qh slice (warp-per-output) + partial-q atomic accumulate ----
        if (warp < nk) {
            const int k = k0 + warp;
            const uint4* w = (const uint4*)(g_Wq1T_bf + (size_t)k * STATE); // 128 uint4
            const float4* h4 = (const float4*)hxo;
            float a = 0.0f;
#pragma unroll
            for (int i = 0; i < 4; i++) {
                int c = lane + 32 * i;
                a += bdot(w[c], h4[c * 2], h4[c * 2 + 1]);
            }
            a = wred(a);
            if (lane == 0) s_qh[warp] = tanhf(a + g_A1[(size_t)t * QIN + k]);
        }
        __syncthreads();
        if (tid < QUERY) {
            float pq = (b == 0) ? bq2[tid] : 0.0f;
            for (int w = 0; w < nk; w++)
                pq += s_qh[w] * Wq2[(size_t)(k0 + w) * QUERY + tid];
            atomicAdd(&g_q[tid], pq);
        } else if (b == 147) {
            // zero g_val/g_z for this step's SB (last read was SC(t-1), barrier-separated)
            int i = tid - 256;              // 0..255
            g_val[i] = 0.0f; g_val[i + 256] = 0.0f;
            if (i == 0) g_z = 0.0f;
        }
        grid_sync(tgt, b);

        // ---- SB: scores -> exp -> partial val & z atomic accumulate ----
        if (tid < QUERY) s_q[tid] = g_q[tid];
        __syncthreads();
        {
            const float4* q4 = (const float4*)s_q;
            for (int r = r0 + warp; r < r1; r += 16) {
                uint4 u = ((const uint4*)(g_kbk_bf + (size_t)r * QUERY))[lane]; // 32 uint4/row
                float a = bdot(u, q4[lane * 2], q4[lane * 2 + 1]);
                a = wred(a);
                if (lane == 0) s_e[r - r0] = expf(a);
            }
        }
        __syncthreads();
        {
            const int nl = r1 - r0;
            float a = 0.0f;
            const __nv_bfloat16* kv = g_kbv_bf + (size_t)r0 * VALUE + tid;
#pragma unroll 4
            for (int i = 0; i < nl; i++)
                a += s_e[i] * __bfloat162float(kv[(size_t)i * VALUE]);
            atomicAdd(&g_val[tid], a);
            if (warp == 0) {
                float z = 0.0f;
                for (int i = lane; i < nl; i += 32) z += s_e[i];
                z = wred(z);
                if (lane == 0) atomicAdd(&g_z, z);
            }
        }
        grid_sync(tgt, b);

        // ---- SC: LSTM gates + update; aux blocks write outputs / zero g_q ----
        const float invZ = 1.0f / g_z;
        if (b < 128) {
            s_val[tid] = g_val[tid] * invZ;
        } else if (b == 128) {
            g_dec_in[(size_t)t * DECIN + EMBD + tid] = g_val[tid] * invZ;
        } else if (b == 129) {
            for (int i = tid; i < STATE; i += NT)
                g_dec_in[(size_t)t * DECIN + EMBD + VALUE + i] = hxo[i];
        } else if (b == 130) {
            if (tid < QUERY) g_q[tid] = 0.0f;   // next step's SA accumulation target
        }
        __syncthreads();

        const int sl = warp >> 1;
        const int half = warp & 1;
        const int s = b * 8 + sl;
        float a0 = 0.0f, a1 = 0.0f;
        if (b < 128) {
            const int j0 = half * 2048 + s;   // half0: i | half1: g
            const int j1 = j0 + 1024;         // half0: f | half1: o
            const float4* v4 = (const float4*)s_val;
            const float4* h4 = (const float4*)hxo;
            const uint4* wv0 = (const uint4*)(g_Wihv_bf + (size_t)j0 * VALUE);  // 64 uint4
            const uint4* wv1 = (const uint4*)(g_Wihv_bf + (size_t)j1 * VALUE);
            const uint4* wh0 = (const uint4*)(g_Whh_bf + (size_t)j0 * STATE);   // 128 uint4
            const uint4* wh1 = (const uint4*)(g_Whh_bf + (size_t)j1 * STATE);
#pragma unroll
            for (int i = 0; i < 2; i++) {
                int c = lane + 32 * i;
                float4 va = v4[c * 2], vb = v4[c * 2 + 1];
                a0 += bdot(wv0[c], va, vb);
                a1 += bdot(wv1[c], va, vb);
            }
#pragma unroll
            for (int i = 0; i < 4; i++) {
                int c = lane + 32 * i;
                float4 ha = h4[c * 2], hb = h4[c * 2 + 1];
                a0 += bdot(wh0[c], ha, hb);
                a1 += bdot(wh1[c], ha, hb);
            }
            a0 = wred(a0); a1 = wred(a1);
            if (lane == 0) {
                a0 += g_Gx[(size_t)t * 4096 + j0];
                a1 += g_Gx[(size_t)t * 4096 + j1];
                if (half) { s_go[sl * 2] = a0; s_go[sl * 2 + 1] = a1; }
            }
        }
        __syncthreads();
        if (b < 128 && half == 0 && lane == 0) {
            float gg = s_go[sl * 2], oo = s_go[sl * 2 + 1];
            float c_old = g_cx[s];
            float cn = sigmoidf_(a1) * c_old + sigmoidf_(a0) * tanhf(gg);
            float hn = sigmoidf_(oo) * tanhf(cn);
            g_cx[s] = cn;
            hxn[s] = hn;
        }
        grid_sync(tgt, b);
    }
}

// ---------------- launch 6: dec_in -> bf16 ----------------
__global__ void conv_dec_kernel() {
    int i = blockIdx.x * blockDim.x + threadIdx.x;  // float4 index
    if (i < SEQ * DECIN / 4) {
        float4 v = ((const float4*)g_dec_in)[i];
        ((__nv_bfloat162*)g_dec_bf)[i * 2]     = __floats2bfloat162_rn(v.x, v.y);
        ((__nv_bfloat162*)g_dec_bf)[i * 2 + 1] = __floats2bfloat162_rn(v.z, v.w);
    }
}

// ---------------- launch 7: bf16 tensor-core decoder: C = A[2048,2560] @ B[32000,2560]^T ----------------
__global__ __launch_bounds__(256) void decoder_wmma_kernel(float* __restrict__ C) {
    __shared__ __nv_bfloat16 As[128][40];
    __shared__ __nv_bfloat16 Bs[128][40];
    const int m0 = blockIdx.y * 128, n0 = blockIdx.x * 128;
    const int tid = threadIdx.x;
    const int warp = tid >> 5;
    const int wm = warp >> 2, wn = warp & 3;   // 2 x 4 warps: warp tile 64 x 32
    const int lr = tid >> 2;                   // 0..63
    const int lc = (tid & 3) * 8;              // 0,8,16,24

    wmma::fragment<wmma::accumulator, 16, 16, 16, float> acc[4][2];
#pragma unroll
    for (int i = 0; i < 4; i++)
#pragma unroll
        for (int j = 0; j < 2; j++) wmma::fill_fragment(acc[i][j], 0.0f);

    for (int k0 = 0; k0 < DECIN; k0 += 32) {
        *(uint4*)&As[lr][lc]      = *(const uint4*)&g_dec_bf[(size_t)(m0 + lr) * DECIN + k0 + lc];
        *(uint4*)&As[lr + 64][lc] = *(const uint4*)&g_dec_bf[(size_t)(m0 + lr + 64) * DECIN + k0 + lc];
        *(uint4*)&Bs[lr][lc]      = *(const uint4*)&g_Wdec_bf[(size_t)(n0 + lr) * DECIN + k0 + lc];
        *(uint4*)&Bs[lr + 64][lc] = *(const uint4*)&g_Wdec_bf[(size_t)(n0 + lr + 64) * DECIN + k0 + lc];
        __syncthreads();
#pragma unroll
        for (int kk = 0; kk < 2; kk++) {
            wmma::fragment<wmma::matrix_a, 16, 16, 16, __nv_bfloat16, wmma::row_major> af[4];
            wmma::fragment<wmma::matrix_b, 16, 16, 16, __nv_bfloat16, wmma::col_major> bf[2];
#pragma unroll
            for (int i = 0; i < 4; i++)
                wmma::load_matrix_sync(af[i], &As[wm * 64 + i * 16][kk * 16], 40);
#pragma unroll
            for (int j = 0; j < 2; j++)
                wmma::load_matrix_sync(bf[j], &Bs[wn * 32 + j * 16][kk * 16], 40);
#pragma unroll
            for (int i = 0; i < 4; i++)
#pragma unroll
                for (int j = 0; j < 2; j++)
                    wmma::mma_sync(acc[i][j], af[i], bf[j], acc[i][j]);
        }
        __syncthreads();
    }
#pragma unroll
    for (int i = 0; i < 4; i++)
#pragma unroll
        for (int j = 0; j < 2; j++)
            wmma::store_matrix_sync(&C[(size_t)(m0 + wm * 64 + i * 16) * NTOK + n0 + wn * 32 + j * 16],
                                    acc[i][j], NTOK, wmma::mem_row_major);
}

// ---------------- launch 8: row-wise log_softmax (folds in decoder bias) ----------------
__global__ __launch_bounds__(256) void logsoftmax_kernel(float* __restrict__ out,
                                                         const float* __restrict__ bias) {
    __shared__ float red[8];
    const int row = blockIdx.x;
    float* x = out + (size_t)row * NTOK;
    const int tid = threadIdx.x;

    float m = -1e30f;
    for (int i = tid; i < NTOK; i += 256) m = fmaxf(m, x[i] + bias[i]);
#pragma unroll
    for (int o = 16; o; o >>= 1) m = fmaxf(m, __shfl_xor_sync(0xffffffffu, m, o));
    if ((tid & 31) == 0) red[tid >> 5] = m;
    __syncthreads();
    float mm = red[0];
#pragma unroll
    for (int i = 1; i < 8; i++) mm = fmaxf(mm, red[i]);
    __syncthreads();

    float sum = 0.0f;
    for (int i = tid; i < NTOK; i += 256) sum += expf(x[i] + bias[i] - mm);
    sum = wred(sum);
    if ((tid & 31) == 0) red[tid >> 5] = sum;
    __syncthreads();
    float ss = 0.0f;
#pragma unroll
    for (int i = 0; i < 8; i++) ss += red[i];
    float lse = mm + logf(ss);

    for (int i = tid; i < NTOK; i += 256) x[i] = x[i] + bias[i] - lse;
}

// ---------------- launch ----------------
extern "C" void kernel_launch(void* const* d_in, const int* in_sizes, int n_in,
                              void* d_out, int out_size) {
    const int*   ids  = (const int*)d_in[0];
    const float* encW = (const float*)d_in[1];
    const float* Wq1  = (const float*)d_in[2];
    const float* bq1  = (const float*)d_in[3];
    const float* Wq2  = (const float*)d_in[4];
    const float* bq2  = (const float*)d_in[5];
    const float* kbk  = (const float*)d_in[6];
    const float* kbv  = (const float*)d_in[7];
    const float* Wih  = (const float*)d_in[8];
    const float* bih  = (const float*)d_in[9];
    const float* Whh  = (const float*)d_in[10];
    const float* bhh  = (const float*)d_in[11];
    const float* Wdec = (const float*)d_in[12];
    const float* bdec = (const float*)d_in[13];
    float* out = (float*)d_out;

    float *p_dec, *p_A1, *p_Gx;
    cudaGetSymbolAddress((void**)&p_dec, g_dec_in);
    cudaGetSymbolAddress((void**)&p_A1,  g_A1);
    cudaGetSymbolAddress((void**)&p_Gx,  g_Gx);

    // launch 0
    embed_init_kernel<<<SEQ, 256>>>(ids, encW);
    // launch 1: all bf16 conversions fused
    conv_all_kernel<<<(N4_TOT + 255) / 256, 256>>>(kbk, kbv, Whh, Wdec, Wih);
    // launch 2: Wq1 transpose (hx rows)
    transpose_wq1_kernel<<<dim3(QIN / 32, STATE / 32), dim3(32, 8)>>>(Wq1);
    // launch 3: A1 = emb @ Wq1[1024:, :] + bq1
    sgemm_kernel<false><<<dim3(QIN / 128, SEQ / 128), 256>>>(
        p_dec, DECIN, Wq1 + (size_t)STATE * QIN, QIN, p_A1, QIN, EMBD, bq1, nullptr);
    // launch 4: Gx = emb @ W_ih[:, :1024]^T + b_ih + b_hh
    sgemm_kernel<true><<<dim3(4096 / 128, SEQ / 128), 256>>>(
        p_dec, DECIN, Wih, LSTMIN, p_Gx, 4096, EMBD, bih, bhh);
    // launch 5: sequential recurrence (persistent, 3 tree barriers/step)
    recurrent_kernel<<<NB, NT>>>(Wq2, bq2);
    // launch 6: convert decoder input to bf16
    conv_dec_kernel<<<(SEQ * DECIN / 4 + 255) / 256, 256>>>();
    // launch 7: decoder tensor-core GEMM
    decoder_wmma_kernel<<<dim3(NTOK / 128, SEQ / 128), 256>>>(out);
    // launch 8: fused-bias log_softmax
    logsoftmax_kernel<<<SEQ, 256>>>(out, bdec);
}